// round 17
// baseline (speedup 1.0000x reference)
#include <cuda_runtime.h>
#include <cuda_bf16.h>
#include <cuda_fp16.h>
#include <cstdint>

#define F0 339
#define F1 5825
#define F2 64
#define NROWS 6228
#define RK 128
#define CH 256

__device__ __align__(16) float g_Q[NROWS * CH];
// kA weights (bf16 hi/lo planes)
__device__ __align__(16) __nv_bfloat16 g_W1hi[256 * 128], g_W1lo[256 * 128];         // conv1 [c][r]
__device__ __align__(16) __nv_bfloat16 g_W2hi[3 * 256 * 256], g_W2lo[3 * 256 * 256]; // [m][d][c]
// kB weights (fp16, single plane)
__device__ __align__(16) __half g_WF[256 * 256];                                     // fc1 [j][k]

// ============================ primitives ============================
__device__ __forceinline__ uint32_t smem_u32(const void* p) {
    uint32_t a;
    asm("{ .reg .u64 t; cvta.to.shared.u64 t, %1; cvt.u32.u64 %0, t; }" : "=r"(a) : "l"(p));
    return a;
}
#define LDSM_X4(r0, r1, r2, r3, addr) \
    asm volatile("ldmatrix.sync.aligned.m8n8.x4.shared.b16 {%0,%1,%2,%3}, [%4];" \
        : "=r"(r0), "=r"(r1), "=r"(r2), "=r"(r3) : "r"(addr))
#define MMA_BF16(d, a, b0, b1) \
    asm volatile("mma.sync.aligned.m16n8k16.row.col.f32.bf16.bf16.f32 " \
        "{%0,%1,%2,%3}, {%4,%5,%6,%7}, {%8,%9}, {%0,%1,%2,%3};" \
        : "+f"((d)[0]), "+f"((d)[1]), "+f"((d)[2]), "+f"((d)[3]) \
        : "r"((a)[0]), "r"((a)[1]), "r"((a)[2]), "r"((a)[3]), "r"(b0), "r"(b1))
#define MMA_F16(d, a, b0, b1) \
    asm volatile("mma.sync.aligned.m16n8k16.row.col.f32.f16.f16.f32 " \
        "{%0,%1,%2,%3}, {%4,%5,%6,%7}, {%8,%9}, {%0,%1,%2,%3};" \
        : "+f"((d)[0]), "+f"((d)[1]), "+f"((d)[2]), "+f"((d)[3]) \
        : "r"((a)[0]), "r"((a)[1]), "r"((a)[2]), "r"((a)[3]), "r"(b0), "r"(b1))
#define CP_ASYNC16(dst, src) \
    asm volatile("cp.async.cg.shared.global [%0], [%1], 16;" :: "r"(dst), "l"(src))
#define CP_COMMIT() asm volatile("cp.async.commit_group;" ::: "memory")
#define CP_WAIT0()  asm volatile("cp.async.wait_group 0;" ::: "memory")
#define CP_WAIT1()  asm volatile("cp.async.wait_group 1;" ::: "memory")

__device__ __forceinline__ void bfsplit(float x, __nv_bfloat16& h, __nv_bfloat16& l) {
    h = __float2bfloat16_rn(x);
    l = __float2bfloat16_rn(x - __bfloat162float(h));
}
__device__ __forceinline__ uint32_t pk(__nv_bfloat16 a, __nv_bfloat16 b) {
    __nv_bfloat162 t; t.x = a; t.y = b;
    return *reinterpret_cast<uint32_t*>(&t);
}
__device__ __forceinline__ uint32_t pkh(__half a, __half b) {
    __half2 t; t.x = a; t.y = b;
    return *reinterpret_cast<uint32_t*>(&t);
}
__device__ __forceinline__ float frelu(float x) { return x > 0.f ? x : 0.f; }

// ============================ kA staging (256 thr, 80B rows) ============================
__device__ __forceinline__ void stageB_256(uint32_t dbuf,
    const __nv_bfloat16* __restrict__ gBhi, const __nv_bfloat16* __restrict__ gBlo,
    int Ksrc, int c, int tid)
{
    #pragma unroll
    for (int it = 0; it < 8; ++it) {
        int idx = tid + it * 256;
        int pl = idx >> 10, rem = idx & 1023;
        int n = rem >> 2, g = rem & 3;
        const __nv_bfloat16* src = (pl ? gBlo : gBhi) + n * Ksrc + c * 32 + g * 8;
        CP_ASYNC16(dbuf + (uint32_t)(pl * 20480 + n * 80 + g * 16), src);
    }
    CP_COMMIT();
}

// ============================ bf16x3 mainloop (kA; 256 thr, 8 warps, M=64, DB) ============================
template<int NCHUNK, int NG>
__device__ __forceinline__ void gemm_bf16x3_256(
    uint32_t sbA, uint32_t sbB,
    const __nv_bfloat16* __restrict__ gBhi, const __nv_bfloat16* __restrict__ gBlo,
    int Ksrc, float (&acc)[2][8][4])
{
    const int tid = threadIdx.x;
    const int lane = tid & 31;
    const int w = tid >> 5;
    const int wm = w & 1, wn = w >> 1;
    const int q = lane >> 3, rl = lane & 7;
    constexpr uint32_t APLANE = 64u * NG * 16u;

    stageB_256(sbB, gBhi, gBlo, Ksrc, 0, tid);

    const int rA0 = wm * 32 + rl + (q & 1) * 8;
    const int nB0 = wn * 64 + rl + (q >> 1) * 8;
    const int gA  = (q >> 1);
    const int gB  = (q & 1);

    for (int c = 0; c < NCHUNK; ++c) {
        if (c + 1 < NCHUNK) {
            stageB_256(sbB + (uint32_t)(((c + 1) & 1) * 40960), gBhi, gBlo, Ksrc, c + 1, tid);
            CP_WAIT1();
        } else CP_WAIT0();
        __syncthreads();
        uint32_t cur = sbB + (uint32_t)((c & 1) * 40960);

        #pragma unroll
        for (int ks = 0; ks < 2; ++ks) {
            uint32_t ah[2][4], al[2][4];
            #pragma unroll
            for (int mt = 0; mt < 2; ++mt) {
                int r = rA0 + mt * 16;
                int g = c * 4 + ks * 2 + gA;
                uint32_t ad = sbA + (uint32_t)((r * NG + (g ^ (r & 7))) << 4);
                LDSM_X4(ah[mt][0], ah[mt][1], ah[mt][2], ah[mt][3], ad);
                LDSM_X4(al[mt][0], al[mt][1], al[mt][2], al[mt][3], ad + APLANE);
            }
            #pragma unroll
            for (int ntp = 0; ntp < 4; ++ntp) {
                int n = nB0 + ntp * 16;
                uint32_t bd = cur + (uint32_t)(n * 80 + (ks * 2 + gB) * 16);
                uint32_t bh[4], bl[4];
                LDSM_X4(bh[0], bh[1], bh[2], bh[3], bd);
                LDSM_X4(bl[0], bl[1], bl[2], bl[3], bd + 20480);
                #pragma unroll
                for (int mt = 0; mt < 2; ++mt) {
                    MMA_BF16(acc[mt][ntp * 2],     ah[mt], bh[0], bh[1]);
                    MMA_BF16(acc[mt][ntp * 2],     al[mt], bh[0], bh[1]);
                    MMA_BF16(acc[mt][ntp * 2],     ah[mt], bl[0], bl[1]);
                    MMA_BF16(acc[mt][ntp * 2 + 1], ah[mt], bh[2], bh[3]);
                    MMA_BF16(acc[mt][ntp * 2 + 1], al[mt], bh[2], bh[3]);
                    MMA_BF16(acc[mt][ntp * 2 + 1], ah[mt], bl[2], bl[3]);
                }
            }
        }
        __syncthreads();
    }
}

// ============================ kW: split weights ============================
__global__ __launch_bounds__(256) void kW(
    const float* __restrict__ w1, const float* __restrict__ wfc1, const float* __restrict__ w2)
{
    int e = blockIdx.x * 256 + threadIdx.x;
    if (e < 32768) {                       // w1 [c][r] bf16 split
        __nv_bfloat16 h, l;
        bfsplit(w1[e], h, l);
        g_W1hi[e] = h; g_W1lo[e] = l;
    } else if (e < 98304) {                // wfc1 [j][k] fp16 single (rn)
        int i = e - 32768;
        g_WF[i] = __float2half_rn(wfc1[i]);
    } else {                               // w2 [d][c][m] -> [m][d][c] bf16 split
        int i = e - 98304;
        int m = i >> 16, r = i & 65535, d = r >> 8, cc = r & 255;
        __nv_bfloat16 h, l;
        bfsplit(w2[d * 768 + cc * 3 + m], h, l);
        g_W2hi[i] = h; g_W2lo[i] = l;
    }
}

// ============================ kA: precompute Q (bf16x3, 99 CTAs x 256 thr, M=64) ============================
// smem: P planes [0,65536); staging DB [65536,147456); E planes [147456,180224); b1s [180224,181248)
#define KA_P    0u
#define KA_STG  65536u
#define KA_AE   147456u
#define KA_B1   180224
#define SMEM_KA 181248

__global__ __launch_bounds__(256) void kA(
    const float* __restrict__ emb0, const float* __restrict__ emb1,
    const float* __restrict__ emb2, const float* __restrict__ b1)
{
    extern __shared__ char smc[];
    const uint32_t sb = smem_u32(smc);
    float* b1s = (float*)(smc + KA_B1);
    const int tid = threadIdx.x;
    const int lane = tid & 31, w = tid >> 5;
    const int wm = w & 1, wn = w >> 1;
    const int g4 = lane >> 2, tig = lane & 3;

    // 64-row blocks: 6 (F0) + 92 (F1) + 1 (F2) = 99
    int b = blockIdx.x, table, gbase, lbase, rows;
    if (b < 6)       { table = 0; int f = b * 64;        lbase = f; gbase = f;           rows = min(64, F0 - f); }
    else if (b < 98) { table = 1; int f = (b - 6) * 64;  lbase = f; gbase = F0 + f;      rows = min(64, F1 - f); }
    else             { table = 2; lbase = 0;             gbase = F0 + F1;                rows = F2; }
    const float* E = (table == 0) ? emb0 : ((table == 1) ? emb1 : emb2);

    b1s[tid] = b1[tid];

    // fill E planes: 64 rows x 16 granules, clamped rows
    {
        #pragma unroll
        for (int it = 0; it < 4; ++it) {
            int idx = tid + it * 256;
            int row = idx >> 4, g = idx & 15;
            int er = lbase + min(row, rows - 1);
            const float4* src = (const float4*)(E + (long long)er * RK + g * 8);
            float4 v0 = src[0], v1 = src[1];
            __nv_bfloat16 h[8], l[8];
            bfsplit(v0.x, h[0], l[0]); bfsplit(v0.y, h[1], l[1]);
            bfsplit(v0.z, h[2], l[2]); bfsplit(v0.w, h[3], l[3]);
            bfsplit(v1.x, h[4], l[4]); bfsplit(v1.y, h[5], l[5]);
            bfsplit(v1.z, h[6], l[6]); bfsplit(v1.w, h[7], l[7]);
            uint32_t off = KA_AE + (uint32_t)((row * 16 + (g ^ (row & 7))) << 4);
            *(uint4*)(smc + off) = make_uint4(pk(h[0], h[1]), pk(h[2], h[3]), pk(h[4], h[5]), pk(h[6], h[7]));
            *(uint4*)(smc + off + 16384) = make_uint4(pk(l[0], l[1]), pk(l[2], l[3]), pk(l[4], l[5]), pk(l[6], l[7]));
        }
    }
    __syncthreads();

    // phase 1: P = relu(E @ W1^T + b1)   (M=64, N=256, K=128)
    float acc[2][8][4];
    #pragma unroll
    for (int mt = 0; mt < 2; mt++)
        #pragma unroll
        for (int nt = 0; nt < 8; nt++)
            #pragma unroll
            for (int p = 0; p < 4; p++) acc[mt][nt][p] = 0.f;
    gemm_bf16x3_256<4, 16>(sb + KA_AE, sb + KA_STG, g_W1hi, g_W1lo, 128, acc);

    // phase1 epilogue -> P planes (NG=32, 64 rows, lo at +32768)
    #pragma unroll
    for (int mt = 0; mt < 2; ++mt) {
        #pragma unroll
        for (int nt = 0; nt < 8; ++nt) {
            int j0 = wn * 64 + nt * 8 + tig * 2;
            float v00 = frelu(acc[mt][nt][0] + b1s[j0]);
            float v01 = frelu(acc[mt][nt][1] + b1s[j0 + 1]);
            float v10 = frelu(acc[mt][nt][2] + b1s[j0]);
            float v11 = frelu(acc[mt][nt][3] + b1s[j0 + 1]);
            __nv_bfloat16 h0, l0, h1, l1;
            int rlo = wm * 32 + mt * 16 + g4;
            int rhi = rlo + 8;
            uint32_t offL = KA_P + (uint32_t)(((rlo * 32 + ((j0 >> 3) ^ (rlo & 7))) << 4) + (j0 & 7) * 2);
            uint32_t offH = KA_P + (uint32_t)(((rhi * 32 + ((j0 >> 3) ^ (rhi & 7))) << 4) + (j0 & 7) * 2);
            bfsplit(v00, h0, l0); bfsplit(v01, h1, l1);
            *(uint32_t*)(smc + offL) = pk(h0, h1);
            *(uint32_t*)(smc + offL + 32768) = pk(l0, l1);
            bfsplit(v10, h0, l0); bfsplit(v11, h1, l1);
            *(uint32_t*)(smc + offH) = pk(h0, h1);
            *(uint32_t*)(smc + offH + 32768) = pk(l0, l1);
        }
    }
    __syncthreads();

    // phase 2: Q = P @ W2m^T   (M=64, N=256, K=256)
    #pragma unroll
    for (int mt = 0; mt < 2; mt++)
        #pragma unroll
        for (int nt = 0; nt < 8; nt++)
            #pragma unroll
            for (int p = 0; p < 4; p++) acc[mt][nt][p] = 0.f;
    gemm_bf16x3_256<8, 32>(sb + KA_P, sb + KA_STG,
                           g_W2hi + table * 65536, g_W2lo + table * 65536, 256, acc);

    #pragma unroll
    for (int mt = 0; mt < 2; ++mt) {
        int rlo = wm * 32 + mt * 16 + g4;
        int rhi = rlo + 8;
        #pragma unroll
        for (int nt = 0; nt < 8; ++nt) {
            int j0 = wn * 64 + nt * 8 + tig * 2;
            if (rlo < rows) {
                float2 v = make_float2(acc[mt][nt][0], acc[mt][nt][1]);
                *(float2*)(g_Q + (gbase + rlo) * CH + j0) = v;
            }
            if (rhi < rows) {
                float2 v = make_float2(acc[mt][nt][2], acc[mt][nt][3]);
                *(float2*)(g_Q + (gbase + rhi) * CH + j0) = v;
            }
        }
    }
}

// ============================ kB: single-pass fp16, 512 thr / 128 samples, 2 CTA/SM ============================
// A: 128 rows x 512B single fp16 plane (XOR g^(r&7)) = 65536 B
// B: DB x 16384 B single plane, packed 64B rows, swizzle g^((n>>1)&3)
#define KB_A    0u
#define KB_STG  65536u
#define KB_BUF  16384u
#define KB_IDX  98304
#define KB_BF1  99840
#define KB_WF2  100864
#define KB_PS   101888
#define KB_FLAG 103936
#define SMEM_KB 103952

__device__ __forceinline__ void stageBf(uint32_t dbuf, int c, int tid)
{
    #pragma unroll
    for (int it = 0; it < 2; ++it) {
        int idx = tid + it * 512;
        int n = idx >> 2, g = idx & 3;
        const __half* src = g_WF + n * 256 + c * 32 + g * 8;
        CP_ASYNC16(dbuf + (uint32_t)(n * 64 + ((g ^ ((n >> 1) & 3)) << 4)), src);
    }
    CP_COMMIT();
}

__global__ __launch_bounds__(512, 2) void kB(
    const void* __restrict__ indices,
    const float* __restrict__ b2,
    const float* __restrict__ bfc1,
    const float* __restrict__ wfc2, const float* __restrict__ bfc2,
    float* __restrict__ out, int B)
{
    extern __shared__ char smc[];
    const uint32_t sb = smem_u32(smc);
    int*   idxs = (int*)(smc + KB_IDX);
    float* bf1s = (float*)(smc + KB_BF1);
    float* wf2s = (float*)(smc + KB_WF2);
    float* psum = (float*)(smc + KB_PS);
    int*   flagp = (int*)(smc + KB_FLAG);

    const int tid = threadIdx.x;
    const int lane = tid & 31, w = tid >> 5;
    const int wm = w & 3, wn = w >> 2;
    const int q = lane >> 3, rl = lane & 7;
    const int g4 = lane >> 2, tig = lane & 3;
    const int b0 = blockIdx.x * 128;

    // prestage B chunk 0
    stageBf(sb + KB_STG, 0, tid);

    // index dtype detect (warp 0; dtype-safe read of first 256 words)
    if (w == 0) {
        const uint32_t* rw = (const uint32_t*)indices;
        uint32_t v = rw[lane * 8 + 1] | rw[lane * 8 + 3] | rw[lane * 8 + 5] | rw[lane * 8 + 7];
        int all0 = __all_sync(0xffffffffu, v == 0u);
        if (lane == 0) *flagp = all0;
    }
    if (tid < 256) bf1s[tid] = bfc1[tid];
    else wf2s[tid - 256] = wfc2[tid - 256];
    __syncthreads();

    const int is64 = *flagp;
    if (tid < 128) {
        long long sg = b0 + tid;
        if (sg > (long long)B - 1) sg = B - 1;
        long long bb = sg * 3;
        int i0, i1, i2;
        if (is64) {
            const long long* ip = (const long long*)indices;
            i0 = (int)ip[bb]; i1 = (int)ip[bb + 1]; i2 = (int)ip[bb + 2];
        } else {
            const int* ip = (const int*)indices;
            i0 = ip[bb]; i1 = ip[bb + 1]; i2 = ip[bb + 2];
        }
        idxs[tid * 3] = i0; idxs[tid * 3 + 1] = i1; idxs[tid * 3 + 2] = i2;
    }
    __syncthreads();

    // gather h2 = relu(Q0[i0]+Q1[i1]+Q2[i2]+b2) -> single fp16 A plane
    {
        const float4* Q0 = (const float4*)g_Q;
        const float4* Q1 = (const float4*)(g_Q + F0 * CH);
        const float4* Q2 = (const float4*)(g_Q + (F0 + F1) * CH);
        const float4* b2v = (const float4*)b2;
        float4 d0 = b2v[2 * lane], d1 = b2v[2 * lane + 1];
        #pragma unroll 2
        for (int it = 0; it < 8; ++it) {
            int s = w * 8 + it;
            int i0 = idxs[s * 3], i1 = idxs[s * 3 + 1], i2 = idxs[s * 3 + 2];
            float4 a0 = Q0[i0 * 64 + 2 * lane], a1 = Q0[i0 * 64 + 2 * lane + 1];
            float4 c0 = Q1[i1 * 64 + 2 * lane], c1 = Q1[i1 * 64 + 2 * lane + 1];
            float4 e0 = Q2[i2 * 64 + 2 * lane], e1 = Q2[i2 * 64 + 2 * lane + 1];
            __half h[8];
            h[0] = __float2half_rn(frelu(a0.x + c0.x + e0.x + d0.x));
            h[1] = __float2half_rn(frelu(a0.y + c0.y + e0.y + d0.y));
            h[2] = __float2half_rn(frelu(a0.z + c0.z + e0.z + d0.z));
            h[3] = __float2half_rn(frelu(a0.w + c0.w + e0.w + d0.w));
            h[4] = __float2half_rn(frelu(a1.x + c1.x + e1.x + d1.x));
            h[5] = __float2half_rn(frelu(a1.y + c1.y + e1.y + d1.y));
            h[6] = __float2half_rn(frelu(a1.z + c1.z + e1.z + d1.z));
            h[7] = __float2half_rn(frelu(a1.w + c1.w + e1.w + d1.w));
            uint32_t off = KB_A + (uint32_t)((s * 32 + (lane ^ (s & 7))) << 4);
            *(uint4*)(smc + off) = make_uint4(pkh(h[0], h[1]), pkh(h[2], h[3]), pkh(h[4], h[5]), pkh(h[6], h[7]));
        }
    }

    // mainloop: 8 K-chunks, DB, single fp16 pass
    float acc[2][8][4];
    #pragma unroll
    for (int mt = 0; mt < 2; mt++)
        #pragma unroll
        for (int nt = 0; nt < 8; nt++)
            #pragma unroll
            for (int p = 0; p < 4; p++) acc[mt][nt][p] = 0.f;

    const int rA0 = wm * 32 + rl + (q & 1) * 8;
    const int nB0 = wn * 64 + rl + (q >> 1) * 8;
    const int gA  = (q >> 1);
    const int gB  = (q & 1);

    for (int c = 0; c < 8; ++c) {
        if (c + 1 < 8) {
            stageBf(sb + KB_STG + (uint32_t)(((c + 1) & 1) * KB_BUF), c + 1, tid);
            CP_WAIT1();
        } else CP_WAIT0();
        __syncthreads();
        uint32_t cur = sb + KB_STG + (uint32_t)((c & 1) * KB_BUF);

        #pragma unroll
        for (int ks = 0; ks < 2; ++ks) {
            uint32_t a[2][4];
            #pragma unroll
            for (int mt = 0; mt < 2; ++mt) {
                int r = rA0 + mt * 16;
                int g = c * 4 + ks * 2 + gA;
                uint32_t ad = sb + KB_A + (uint32_t)((r * 32 + (g ^ (r & 7))) << 4);
                LDSM_X4(a[mt][0], a[mt][1], a[mt][2], a[mt][3], ad);
            }
            #pragma unroll
            for (int ntp = 0; ntp < 4; ++ntp) {
                int n = nB0 + ntp * 16;
                int kg = ks * 2 + gB;
                uint32_t off = (uint32_t)(n * 64 + ((kg ^ ((n >> 1) & 3)) << 4));
                uint32_t bf[4];
                LDSM_X4(bf[0], bf[1], bf[2], bf[3], cur + off);
                #pragma unroll
                for (int mt = 0; mt < 2; ++mt) {
                    MMA_F16(acc[mt][ntp * 2],     a[mt], bf[0], bf[1]);
                    MMA_F16(acc[mt][ntp * 2 + 1], a[mt], bf[2], bf[3]);
                }
            }
        }
        __syncthreads();
    }

    // epilogue: fc1 bias+relu, fc2 dot, quad reduce, combine 4 N-quadrants
    #pragma unroll
    for (int mt = 0; mt < 2; ++mt) {
        float p0 = 0.f, p1 = 0.f;
        #pragma unroll
        for (int nt = 0; nt < 8; ++nt) {
            int j = wn * 64 + nt * 8 + tig * 2;
            float bj0 = bf1s[j], bj1 = bf1s[j + 1];
            float wj0 = wf2s[j], wj1 = wf2s[j + 1];
            p0 += frelu(acc[mt][nt][0] + bj0) * wj0;
            p0 += frelu(acc[mt][nt][1] + bj1) * wj1;
            p1 += frelu(acc[mt][nt][2] + bj0) * wj0;
            p1 += frelu(acc[mt][nt][3] + bj1) * wj1;
        }
        p0 += __shfl_xor_sync(0xffffffffu, p0, 1);
        p0 += __shfl_xor_sync(0xffffffffu, p0, 2);
        p1 += __shfl_xor_sync(0xffffffffu, p1, 1);
        p1 += __shfl_xor_sync(0xffffffffu, p1, 2);
        if (tig == 0) {
            int r = wm * 32 + mt * 16 + g4;
            psum[wn * 128 + r] = p0;
            psum[wn * 128 + r + 8] = p1;
        }
    }
    __syncthreads();
    if (tid < 128) {
        int sg = b0 + tid;
        if (sg < B)
            out[sg] = frelu(psum[tid] + psum[128 + tid] + psum[256 + tid] + psum[384 + tid] + bfc2[0]);
    }
}

// ============================ launch ============================
extern "C" void kernel_launch(void* const* d_in, const int* in_sizes, int n_in,
                              void* d_out, int out_size)
{
    const void*  indices = d_in[0];
    const float* emb0 = (const float*)d_in[1];
    const float* emb1 = (const float*)d_in[2];
    const float* emb2 = (const float*)d_in[3];
    const float* w1   = (const float*)d_in[4];
    const float* b1   = (const float*)d_in[5];
    const float* w2   = (const float*)d_in[6];
    const float* b2   = (const float*)d_in[7];
    const float* wfc1 = (const float*)d_in[8];
    const float* bfc1 = (const float*)d_in[9];
    const float* wfc2 = (const float*)d_in[10];
    const float* bfc2 = (const float*)d_in[11];
    float* out = (float*)d_out;

    int B = in_sizes[0] / 3;

    cudaFuncSetAttribute(kA, cudaFuncAttributeMaxDynamicSharedMemorySize, SMEM_KA);
    cudaFuncSetAttribute(kB, cudaFuncAttributeMaxDynamicSharedMemorySize, SMEM_KB);

    kW<<<1152, 256>>>(w1, wfc1, w2);
    kA<<<99, 256, SMEM_KA>>>(emb0, emb1, emb2, b1);
    int nb = (B + 127) / 128;
    kB<<<nb, 512, SMEM_KB>>>(indices, b2, bfc1, wfc2, bfc2, out, B);
}